// round 10
// baseline (speedup 1.0000x reference)
#include <cuda_runtime.h>

// QHadamard: y = FWHT_4096(x) / 64, rows = 8192, DIM = 4096.
// R4/R8 structure: 3 register passes, 2 smem transposes, 0 shuffles.
//   A: bits {5..9}  (thread owns e{0..4} lanes + e{10,11} warp; scalar LDG/STS)
//   B: bits {0..4}  (32 contiguous elem/thread; float4 smem in-place)
//   C: bits {10,11} (float4 smem read; dense float4 STG) -- scalar math (reg relief)
// Swizzle phys(e) = e ^ ((e & 0xE0) >> 3) -- conflict-free in all phases.
// R10 change: __launch_bounds__(128,12) -> 42-reg budget, 12 blocks/SM
// (48 warps, +20% concurrency vs R9's 10 blocks). Pass C de-packed to cut
// peak u64 register pressure so the 42-reg point is reachable without spills.

#define DIM 4096
#define THREADS 128

typedef unsigned long long u64;

#define NEG1_F32X2  0xBF800000BF800000ULL   // {-1.0f, -1.0f}
#define SC_F32X2    0x3C8000003C800000ULL   // {1/64, 1/64}

__device__ __forceinline__ void bfly(float& a, float& b) {
    float t = a; a = t + b; b = t - b;
}

__device__ __forceinline__ u64 pack2(float lo, float hi) {
    u64 r;
    asm("mov.b64 %0, {%1, %2};" : "=l"(r) : "f"(lo), "f"(hi));
    return r;
}
__device__ __forceinline__ void unpack2(u64 v, float& lo, float& hi) {
    asm("mov.b64 {%0, %1}, %2;" : "=f"(lo), "=f"(hi) : "l"(v));
}
// Packed butterfly: (a, b) -> (a + b, a - b) on two lanes at once.
__device__ __forceinline__ void pbfly(u64& a, u64& b, u64 neg1) {
    u64 s, d;
    asm("add.rn.f32x2 %0, %1, %2;" : "=l"(s) : "l"(a), "l"(b));
    asm("fma.rn.f32x2 %0, %1, %2, %3;" : "=l"(d) : "l"(b), "l"(neg1), "l"(a));
    a = s; b = d;
}
// FWHT-16 on 16 packed pairs (covers 4 element bits above the packing bit).
__device__ __forceinline__ void pfwht16(u64* v, u64 neg1) {
#pragma unroll
    for (int h = 1; h < 16; h <<= 1)
#pragma unroll
        for (int i = 0; i < 16; i += (h << 1))
#pragma unroll
            for (int j = i; j < i + h; ++j) pbfly(v[j], v[j + h], neg1);
}

// Full 32-point FWHT: scalar stage on bit0, packed stages on bits 1..4.
template <bool DO_SCALE>
__device__ __forceinline__ void fwht32_packed(float* x) {
    const u64 neg1 = NEG1_F32X2;
#pragma unroll
    for (int j = 0; j < 16; ++j) bfly(x[2*j], x[2*j + 1]);   // bit 0, scalar
    u64 v[16];
#pragma unroll
    for (int j = 0; j < 16; ++j) v[j] = pack2(x[2*j], x[2*j + 1]);
    if (DO_SCALE) {
        const u64 sc = SC_F32X2;
#pragma unroll
        for (int j = 0; j < 16; ++j)
            asm("mul.rn.f32x2 %0, %1, %2;" : "=l"(v[j]) : "l"(v[j]), "l"(sc));
    }
    pfwht16(v, neg1);                                        // bits 1..4, packed
#pragma unroll
    for (int j = 0; j < 16; ++j) unpack2(v[j], x[2*j], x[2*j + 1]);
}

__global__ void __launch_bounds__(THREADS, 12)
QHadamard_24524263260380_kernel(const float* __restrict__ in,
                                float* __restrict__ out) {
    __shared__ float s[DIM];                      // 16 KB, swizzled layout

    const int    T   = threadIdx.x;               // 0..127
    const size_t row = (size_t)blockIdx.x * DIM;
    const float* g   = in + row;

    // ---- Pass A: e = (T&31) + k*32 + (T>>5)*1024, k = 0..31 -> bits {5..9} ----
    const int abase = (T & 31) + ((T >> 5) << 10);
    float x[32];
#pragma unroll
    for (int k = 0; k < 32; ++k) x[k] = __ldcs(g + abase + (k << 5));

    fwht32_packed<true>(x);                       // FWHT bits 5..9, scale folded

    // ---- T1 write: s[swz(e)], swz = e ^ ((k&7)<<2). Banks = lane ^ const. ----
#pragma unroll
    for (int k = 0; k < 32; ++k) {
        s[(abase + (k << 5)) ^ ((k & 7) << 2)] = x[k];
    }
    __syncthreads();

    // ---- Pass B: thread T = e>>5 owns 32 contiguous elements. f4 in/out. ----
    float y[32];
    {
        const int base4 = T * 8;                  // float4 index of e = T*32
        float4* s4 = reinterpret_cast<float4*>(s);
#pragma unroll
        for (int r = 0; r < 8; ++r) {
            float4 v = s4[base4 + (r ^ (T & 7))];
            y[r*4+0] = v.x; y[r*4+1] = v.y; y[r*4+2] = v.z; y[r*4+3] = v.w;
        }
        fwht32_packed<false>(y);                  // FWHT bits 0..4
#pragma unroll
        for (int r = 0; r < 8; ++r) {
            s4[base4 + (r ^ (T & 7))] =
                make_float4(y[r*4+0], y[r*4+1], y[r*4+2], y[r*4+3]);
        }
    }
    __syncthreads();

    // ---- Pass C: base bits{2..6}=T&31, {7,8}=(T>>5)&3; owns {0,1,9,10,11} ----
    const int cbase4 = (T & 31) + (((T >> 5) & 3) << 5);   // float4 index
    const int cxor4  = (T >> 3) & 7;                       // swizzle in f4 units
    float z[32];
    {
        const float4* s4 = reinterpret_cast<const float4*>(s);
#pragma unroll
        for (int rr = 0; rr < 4; ++rr)
#pragma unroll
            for (int s9 = 0; s9 < 2; ++s9) {
                float4 v = s4[(cbase4 + (s9 << 7) + (rr << 8)) ^ cxor4];
                const int i = (rr << 3) + (s9 << 2);
                z[i] = v.x; z[i+1] = v.y; z[i+2] = v.z; z[i+3] = v.w;
            }
    }
    // FWHT over bits {10,11} = z-index bits {3,4}: scalar (low reg pressure).
#pragma unroll
    for (int hi = 0; hi < 32; hi += 16)
#pragma unroll
        for (int j = 0; j < 8; ++j) bfly(z[hi + j], z[hi + j + 8]);
#pragma unroll
    for (int j = 0; j < 16; ++j) bfly(z[j], z[j + 16]);

    // ---- Dense float4 streaming stores ----
    float4* o4 = reinterpret_cast<float4*>(out + row);
#pragma unroll
    for (int rr = 0; rr < 4; ++rr)
#pragma unroll
        for (int s9 = 0; s9 < 2; ++s9) {
            const int i = (rr << 3) + (s9 << 2);
            __stcs(o4 + (cbase4 + (s9 << 7) + (rr << 8)),
                   make_float4(z[i], z[i+1], z[i+2], z[i+3]));
        }
}

extern "C" void kernel_launch(void* const* d_in, const int* in_sizes, int n_in,
                              void* d_out, int out_size) {
    const float* x   = (const float*)d_in[0];
    float*       out = (float*)d_out;
    const int rows = in_sizes[0] / DIM;            // 8192
    QHadamard_24524263260380_kernel<<<rows, THREADS>>>(x, out);
}

// round 11
// speedup vs baseline: 1.2221x; 1.2221x over previous
#include <cuda_runtime.h>

// QHadamard: y = FWHT_4096(x) / 64, rows = 8192, DIM = 4096.
// Exact R4 structure (best measured kernel: 39.5us): 3 scalar register passes,
// 2 smem transposes, 0 shuffles, lb(128,8), regs~56 (no spills).
//   A: bits {5..9}  (thread owns e{0..4} lanes + e{10,11} warp; scalar LDG/STS)
//   B: bits {0..4}  (32 contiguous elem/thread; float4 smem in-place)
//   C: bits {10,11} (float4 smem read; dense float4 STG)
// Swizzle phys(e) = e ^ ((e & 0xE0) >> 3) -- conflict-free in all phases.
// R11 change: the A->B exchange is provably INTRA-WARP (pass-B thread T reads
// only elements written by warp(T): source lane = e{0..4}, source warp =
// e{10,11} = T{5,6}), so barrier 1 is __syncwarp() instead of __syncthreads().
// Warps flow A->B independently; only the B->C exchange (which spans e{9..11}
// across warps) keeps a block barrier.

#define DIM 4096
#define THREADS 128

__device__ __forceinline__ void bfly(float& a, float& b) {
    float t = a; a = t + b; b = t - b;
}

__device__ __forceinline__ void fwht32(float* x) {
#pragma unroll
    for (int h = 1; h < 32; h <<= 1)
#pragma unroll
        for (int i = 0; i < 32; i += (h << 1))
#pragma unroll
            for (int j = i; j < i + h; ++j) bfly(x[j], x[j + h]);
}

__global__ void __launch_bounds__(THREADS, 8)
QHadamard_24524263260380_kernel(const float* __restrict__ in,
                                float* __restrict__ out) {
    __shared__ float s[DIM];                      // 16 KB, swizzled layout

    const int    T   = threadIdx.x;               // 0..127
    const size_t row = (size_t)blockIdx.x * DIM;
    const float* g   = in + row;

    // ---- Pass A: e = (T&31) + k*32 + (T>>5)*1024, k = 0..31 -> bits {5..9} ----
    const int abase = (T & 31) + ((T >> 5) << 10);
    float x[32];
#pragma unroll
    for (int k = 0; k < 32; ++k) x[k] = g[abase + (k << 5)];

    const float scale = 0.015625f;                // 1/sqrt(4096)
#pragma unroll
    for (int k = 0; k < 32; ++k) x[k] *= scale;

    fwht32(x);                                    // FWHT over bits 5..9

    // ---- T1 write: s[swz(e)], swz = e ^ ((k&7)<<2). Banks = lane ^ const. ----
#pragma unroll
    for (int k = 0; k < 32; ++k) {
        s[(abase + (k << 5)) ^ ((k & 7) << 2)] = x[k];
    }
    // A->B exchange is intra-warp (see header): warp-local sync suffices.
    __syncwarp(0xffffffffu);

    // ---- Pass B: thread T = e>>5 owns 32 contiguous elements. f4 in/out. ----
    float y[32];
    {
        const int base4 = T * 8;                  // float4 index of e = T*32
        float4* s4 = reinterpret_cast<float4*>(s);
#pragma unroll
        for (int r = 0; r < 8; ++r) {
            float4 v = s4[base4 + (r ^ (T & 7))];
            y[r*4+0] = v.x; y[r*4+1] = v.y; y[r*4+2] = v.z; y[r*4+3] = v.w;
        }
        fwht32(y);                                // FWHT over bits 0..4
#pragma unroll
        for (int r = 0; r < 8; ++r) {
            s4[base4 + (r ^ (T & 7))] =
                make_float4(y[r*4+0], y[r*4+1], y[r*4+2], y[r*4+3]);
        }
    }
    __syncthreads();                              // B->C spans all warps

    // ---- Pass C: base bits{2..6}=T&31, {7,8}=(T>>5)&3; owns {0,1,9,10,11} ----
    const int cbase4 = (T & 31) + (((T >> 5) & 3) << 5);   // float4 index
    const int cxor4  = (T >> 3) & 7;                       // swizzle in f4 units
    float z[32];
    {
        const float4* s4 = reinterpret_cast<const float4*>(s);
#pragma unroll
        for (int rr = 0; rr < 4; ++rr)
#pragma unroll
            for (int s9 = 0; s9 < 2; ++s9) {
                float4 v = s4[(cbase4 + (s9 << 7) + (rr << 8)) ^ cxor4];
                const int i = (rr << 3) + (s9 << 2);
                z[i] = v.x; z[i+1] = v.y; z[i+2] = v.z; z[i+3] = v.w;
            }
    }
    // FWHT over bits {10,11} = z-index bits {3,4}
#pragma unroll
    for (int hi = 0; hi < 32; hi += 16)
#pragma unroll
        for (int j = 0; j < 8; ++j) bfly(z[hi + j], z[hi + j + 8]);
#pragma unroll
    for (int j = 0; j < 16; ++j) bfly(z[j], z[j + 16]);

    // ---- Dense float4 stores: per instr lanes write 32 contiguous float4 ----
    float4* o4 = reinterpret_cast<float4*>(out + row);
#pragma unroll
    for (int rr = 0; rr < 4; ++rr)
#pragma unroll
        for (int s9 = 0; s9 < 2; ++s9) {
            const int i = (rr << 3) + (s9 << 2);
            o4[cbase4 + (s9 << 7) + (rr << 8)] =
                make_float4(z[i], z[i+1], z[i+2], z[i+3]);
        }
}

extern "C" void kernel_launch(void* const* d_in, const int* in_sizes, int n_in,
                              void* d_out, int out_size) {
    const float* x   = (const float*)d_in[0];
    float*       out = (float*)d_out;
    const int rows = in_sizes[0] / DIM;            // 8192
    QHadamard_24524263260380_kernel<<<rows, THREADS>>>(x, out);
}